// round 12
// baseline (speedup 1.0000x reference)
#include <cuda_runtime.h>
#include <cuda_bf16.h>
#include <math.h>
#include <stdint.h>

#define TT 512
#define BB 32
#define II 512
#define HH 1024
#define G3 3072
#define NCTA 128
#define NTHR 256
#define OUT_COPY (TT * BB * HH)

#define KE 1536          // K_eff for input gemm (512*3)
#define WS_ROW 776       // 768 + 8 pad (bf16 elems)
#define WS_BYTES (96 * WS_ROW * 2)          // 148992
#define HS_OFF WS_BYTES
#define SMEM_GRU (WS_BYTES + 32 * WS_ROW * 2)  // 198656

typedef unsigned long long ull;

// -------- static device scratch --------
__device__ float g_gi[(size_t)TT * BB * G3];          // gi = X@w_ih + b_ih
__device__ float g_wT[G3 * HH];                       // w_hh^T fp32 [3H][H]
__device__ __nv_bfloat16 g_xs[(size_t)TT * BB * KE];  // X split [row][hi|hi|lo]
__device__ __nv_bfloat16 g_wst[(size_t)G3 * KE];      // w_ih^T split [n][hi|lo|hi]
__device__ float g_h[2][BB * HH];                     // fp32 hidden [b][k]
__device__ __nv_bfloat16 g_hbf[2][2][BB * HH];        // bf16 hi/lo of h [b][k]
__device__ float g_part[NCTA * BB * 96];              // split-K partials [blk][b][m]
__device__ unsigned g_bar_count = 0;
__device__ volatile unsigned g_bar_phase = 0;

// bf16 mma m16n8k16: D(f32) += A(bf16,row) * B(bf16,col)
static __device__ __forceinline__ void mma_bf16(float* d, const uint32_t* a,
                                                const uint32_t* b) {
    asm volatile(
        "mma.sync.aligned.m16n8k16.row.col.f32.bf16.bf16.f32 "
        "{%0,%1,%2,%3}, {%4,%5,%6,%7}, {%8,%9}, {%0,%1,%2,%3};"
        : "+f"(d[0]), "+f"(d[1]), "+f"(d[2]), "+f"(d[3])
        : "r"(a[0]), "r"(a[1]), "r"(a[2]), "r"(a[3]), "r"(b[0]), "r"(b[1]));
}

static __device__ __forceinline__ void split_bf16(float x, __nv_bfloat16& hi,
                                                  __nv_bfloat16& lo) {
    hi = __float2bfloat16(x);
    lo = __float2bfloat16(x - __bfloat162float(hi));
}

// ============================================================
// Transpose w_hh [H][3H] -> g_wT [3H][H] (fp32)
// ============================================================
__global__ void k_transpose(const float* __restrict__ whh) {
    __shared__ float tile[32][33];
    const int col0 = blockIdx.x * 32;
    const int row0 = blockIdx.y * 32;
    const int tx = threadIdx.x, ty = threadIdx.y;
#pragma unroll
    for (int r = ty; r < 32; r += 8)
        tile[r][tx] = whh[(row0 + r) * G3 + col0 + tx];
    __syncthreads();
#pragma unroll
    for (int r = ty; r < 32; r += 8)
        g_wT[(size_t)(col0 + r) * HH + row0 + tx] = tile[tx][r];
}

// ============================================================
// Split X -> g_xs [hi | hi | lo] along K
// ============================================================
__global__ void k_split_x(const float* __restrict__ X) {
    const size_t idx = (size_t)blockIdx.x * 256 + threadIdx.x;
    const float x = X[idx];
    const size_t r = idx >> 9;          // / 512
    const int k = (int)(idx & 511);
    __nv_bfloat16 hi, lo; split_bf16(x, hi, lo);
    __nv_bfloat16* row = g_xs + r * KE;
    row[k] = hi; row[512 + k] = hi; row[1024 + k] = lo;
}

// ============================================================
// Split+transpose w_ih [512][3072] -> g_wst [3072][hi | lo | hi]
// ============================================================
__global__ void k_split_wt(const float* __restrict__ wih) {
    __shared__ float tile[32][33];
    const int col0 = blockIdx.x * 32;   // 3072 dim
    const int row0 = blockIdx.y * 32;   // 512 dim
    const int tx = threadIdx.x, ty = threadIdx.y;
#pragma unroll
    for (int r = ty; r < 32; r += 8)
        tile[r][tx] = wih[(row0 + r) * G3 + col0 + tx];
    __syncthreads();
#pragma unroll
    for (int r = ty; r < 32; r += 8) {
        const float x = tile[tx][r];
        __nv_bfloat16 hi, lo; split_bf16(x, hi, lo);
        __nv_bfloat16* row = g_wst + (size_t)(col0 + r) * KE + row0 + tx;
        row[0] = hi; row[512] = lo; row[1024] = hi;
    }
}

// ============================================================
// Input GEMM (HMMA bf16x3): gi = X@W + bias.
// M=16384, N=3072, K_eff=1536. BM=BN=128, BK=32, 256 thr (8 warps 4m x 2n).
// ============================================================
__global__ __launch_bounds__(256) void k_gemm_gi(const float* __restrict__ bias) {
    __shared__ __nv_bfloat16 a_s[2][128 * 40];
    __shared__ __nv_bfloat16 b_s[2][128 * 40];

    const int bm = blockIdx.y * 128;
    const int bn = blockIdx.x * 128;
    const int tid = threadIdx.x;
    const int wid = tid >> 5, lane = tid & 31;
    const int g = lane >> 2, tg = lane & 3;
    const int mw = wid & 3, nw = wid >> 2;   // warp tile [mw*32,+32) x [nw*64,+64)

    const int grow = tid >> 1;               // 0..127
    const int gco4 = (tid & 1) * 2;          // uint4 offset within 32-elem chunk

    const uint4* ap = (const uint4*)(g_xs + (size_t)(bm + grow) * KE);
    const uint4* bp = (const uint4*)(g_wst + (size_t)(bn + grow) * KE);

    float acc[2][8][4];
#pragma unroll
    for (int i = 0; i < 2; i++)
#pragma unroll
        for (int j = 0; j < 8; j++)
#pragma unroll
            for (int p = 0; p < 4; p++) acc[i][j][p] = 0.f;

    // prologue: chunk 0
    {
        uint4 av0 = ap[gco4], av1 = ap[gco4 + 1];
        uint4 bv0 = bp[gco4], bv1 = bp[gco4 + 1];
        *(uint4*)&a_s[0][grow * 40 + gco4 * 8] = av0;
        *(uint4*)&a_s[0][grow * 40 + gco4 * 8 + 8] = av1;
        *(uint4*)&b_s[0][grow * 40 + gco4 * 8] = bv0;
        *(uint4*)&b_s[0][grow * 40 + gco4 * 8 + 8] = bv1;
    }
    __syncthreads();

    int buf = 0;
    for (int kc = 0; kc < KE / 32; kc++) {
        uint4 av0, av1, bv0, bv1;
        if (kc < KE / 32 - 1) {
            av0 = ap[(kc + 1) * 4 + gco4]; av1 = ap[(kc + 1) * 4 + gco4 + 1];
            bv0 = bp[(kc + 1) * 4 + gco4]; bv1 = bp[(kc + 1) * 4 + gco4 + 1];
        }
#pragma unroll
        for (int kk = 0; kk < 2; kk++) {
            const int ka = kk * 16 + 2 * tg;
            uint32_t afr[2][4];
#pragma unroll
            for (int mt = 0; mt < 2; mt++) {
                const int ar = mw * 32 + mt * 16 + g;
                afr[mt][0] = *(const uint32_t*)&a_s[buf][ar * 40 + ka];
                afr[mt][1] = *(const uint32_t*)&a_s[buf][(ar + 8) * 40 + ka];
                afr[mt][2] = *(const uint32_t*)&a_s[buf][ar * 40 + ka + 8];
                afr[mt][3] = *(const uint32_t*)&a_s[buf][(ar + 8) * 40 + ka + 8];
            }
#pragma unroll
            for (int nt = 0; nt < 8; nt++) {
                const int br = nw * 64 + nt * 8 + g;
                uint32_t bfr[2];
                bfr[0] = *(const uint32_t*)&b_s[buf][br * 40 + ka];
                bfr[1] = *(const uint32_t*)&b_s[buf][br * 40 + ka + 8];
                mma_bf16(acc[0][nt], afr[0], bfr);
                mma_bf16(acc[1][nt], afr[1], bfr);
            }
        }
        if (kc < KE / 32 - 1) {
            *(uint4*)&a_s[buf ^ 1][grow * 40 + gco4 * 8] = av0;
            *(uint4*)&a_s[buf ^ 1][grow * 40 + gco4 * 8 + 8] = av1;
            *(uint4*)&b_s[buf ^ 1][grow * 40 + gco4 * 8] = bv0;
            *(uint4*)&b_s[buf ^ 1][grow * 40 + gco4 * 8 + 8] = bv1;
            __syncthreads();
            buf ^= 1;
        }
    }

    // epilogue: D[m][n] -> gi[row][col] + bias
#pragma unroll
    for (int mt = 0; mt < 2; mt++) {
        const int row0 = bm + mw * 32 + mt * 16 + g;
#pragma unroll
        for (int nt = 0; nt < 8; nt++) {
            const int col = bn + nw * 64 + nt * 8 + 2 * tg;
            const float bz0 = __ldg(bias + col), bz1 = __ldg(bias + col + 1);
            float2 o0 = make_float2(acc[mt][nt][0] + bz0, acc[mt][nt][1] + bz1);
            float2 o1 = make_float2(acc[mt][nt][2] + bz0, acc[mt][nt][3] + bz1);
            *(float2*)&g_gi[(size_t)row0 * G3 + col] = o0;
            *(float2*)&g_gi[(size_t)(row0 + 8) * G3 + col] = o1;
        }
    }
}

// ============================================================
// Grid-wide barrier (128 CTAs, all wave-1 resident)
// ============================================================
__device__ __forceinline__ void grid_bar(unsigned& phase) {
    __syncthreads();
    if (threadIdx.x == 0) {
        unsigned old = atomicAdd(&g_bar_count, 1u);
        if (old == NCTA - 1) {
            g_bar_count = 0;
            __threadfence();
            g_bar_phase = phase + 1;
        } else {
            while (g_bar_phase == phase) { }
        }
        __threadfence();
    }
    __syncthreads();
    phase++;
}

// ============================================================
// Persistent GRU recurrence (HMMA bf16x3).
// 128 CTAs x 256 thr. blk = cg*4+s: cg -> 96 cols of 3H, s -> K seg of 256.
// w smem [96][776]: [whi|whi|wlo]; h smem [32][776]: [hhi|hlo|hhi].
// GEMM: warps 0..5, warp = m-tile (16 cols), all 4 n-tiles (batch), K_eff=768.
// Partials to g_part; gates distributed over all 128 CTAs (1 item/thread).
// ============================================================
__global__ __launch_bounds__(NTHR, 1) void k_gru(const float* __restrict__ paddings,
                                                 const float* __restrict__ b_hh,
                                                 float* __restrict__ out,
                                                 int copies) {
    extern __shared__ char sm8[];
    __nv_bfloat16* w_s = (__nv_bfloat16*)sm8;            // [96][776]
    __nv_bfloat16* h_s = (__nv_bfloat16*)(sm8 + HS_OFF); // [32][776]
    float* tb = (float*)(sm8 + HS_OFF);                  // alias after GEMM: [32][100]

    const int tid = threadIdx.x;
    const int wid = tid >> 5, lane = tid & 31;
    const int g = lane >> 2, tg = lane & 3;
    const int blk = blockIdx.x, cg = blk >> 2, s = blk & 3;

    // ---- stage w slice once: [96 m][256 k] -> [hi|hi|lo] ----
    for (int idx = tid; idx < 96 * 256; idx += NTHR) {
        const int m = idx >> 8, k = idx & 255;
        __nv_bfloat16 hi, lo;
        split_bf16(g_wT[(size_t)(cg * 96 + m) * HH + s * 256 + k], hi, lo);
        w_s[m * WS_ROW + k] = hi;
        w_s[m * WS_ROW + 256 + k] = hi;
        w_s[m * WS_ROW + 512 + k] = lo;
    }

    // ---- gate-thread constants (all CTAs: 8 hidden dims x 32 batches) ----
    const int k0 = blk * 8 + (tid & 7);
    const int b0 = tid >> 3;
    const float bhr = b_hh[k0], bhz = b_hh[HH + k0], bhn = b_hh[2 * HH + k0];
    const float* pb[3];
#pragma unroll
    for (int g3 = 0; g3 < 3; g3++) {
        const int col = g3 * HH + k0;
        pb[g3] = g_part + (size_t)((col / 96) * 4) * 3072 + b0 * 96 + (col % 96);
    }

    // init h buffer 0
    g_h[0][b0 * HH + k0] = 0.f;
    g_hbf[0][0][b0 * HH + k0] = __float2bfloat16(0.f);
    g_hbf[0][1][b0 * HH + k0] = __float2bfloat16(0.f);
    __threadfence();

    unsigned phase = g_bar_phase;
    grid_bar(phase);

    for (int t = 0; t < TT; t++) {
        // ---- stage h seg: [32 b][256 k] hi/lo -> [hhi|hlo|hhi] ----
        const uint4* hhi = (const uint4*)g_hbf[t & 1][0];
        const uint4* hlo = (const uint4*)g_hbf[t & 1][1];
#pragma unroll 2
        for (int idx = tid; idx < 1024; idx += NTHR) {
            const int b = idx >> 5, u = idx & 31;
            const uint4 vhi = __ldcg(&hhi[b * 128 + s * 32 + u]);
            const uint4 vlo = __ldcg(&hlo[b * 128 + s * 32 + u]);
            __nv_bfloat16* hrow = h_s + b * WS_ROW + u * 8;
            *(uint4*)(hrow) = vhi;
            *(uint4*)(hrow + 256) = vlo;
            *(uint4*)(hrow + 512) = vhi;
        }
        __syncthreads();

        // ---- GEMM: warps 0..5 ----
        float acc[4][4];
        if (wid < 6) {
#pragma unroll
            for (int nt = 0; nt < 4; nt++)
#pragma unroll
                for (int p = 0; p < 4; p++) acc[nt][p] = 0.f;
            const int ar = wid * 16 + g;
#pragma unroll 4
            for (int kk = 0; kk < 48; kk++) {
                const int ka = kk * 16 + 2 * tg;
                uint32_t afr[4];
                afr[0] = *(const uint32_t*)&w_s[ar * WS_ROW + ka];
                afr[1] = *(const uint32_t*)&w_s[(ar + 8) * WS_ROW + ka];
                afr[2] = *(const uint32_t*)&w_s[ar * WS_ROW + ka + 8];
                afr[3] = *(const uint32_t*)&w_s[(ar + 8) * WS_ROW + ka + 8];
#pragma unroll
                for (int nt = 0; nt < 4; nt++) {
                    const int br = nt * 8 + g;
                    uint32_t bfr[2];
                    bfr[0] = *(const uint32_t*)&h_s[br * WS_ROW + ka];
                    bfr[1] = *(const uint32_t*)&h_s[br * WS_ROW + ka + 8];
                    mma_bf16(acc[nt], afr, bfr);
                }
            }
        }
        __syncthreads();   // all h reads done -> tb alias safe

        // ---- epilogue: D frags -> tb[b][m] ----
        if (wid < 6) {
            const int m0 = wid * 16 + g;
#pragma unroll
            for (int nt = 0; nt < 4; nt++) {
                const int bcol = nt * 8 + 2 * tg;
                tb[bcol * 100 + m0] = acc[nt][0];
                tb[(bcol + 1) * 100 + m0] = acc[nt][1];
                tb[bcol * 100 + m0 + 8] = acc[nt][2];
                tb[(bcol + 1) * 100 + m0 + 8] = acc[nt][3];
            }
        }
        __syncthreads();

        // ---- copy tb -> g_part[blk] ----
        float* gp = g_part + (size_t)blk * 3072;
#pragma unroll
        for (int i = tid; i < 768; i += NTHR) {
            const int b = i / 24, o = i - b * 24;
            *(uint4*)&gp[b * 96 + o * 4] = *(const uint4*)&tb[b * 100 + o * 4];
        }
        __threadfence();
        grid_bar(phase);

        // ---- gates (all CTAs, 1 item/thread) ----
        {
            const float* gib = g_gi + (size_t)t * BB * G3 + (size_t)b0 * G3;
            const float gir = __ldg(gib + k0);
            const float giz = __ldg(gib + HH + k0);
            const float gin = __ldg(gib + 2 * HH + k0);
            const float p = __ldg(paddings + t * BB + b0);
            float gh[3];
#pragma unroll
            for (int g3 = 0; g3 < 3; g3++)
                gh[g3] = __ldcg(pb[g3]) + __ldcg(pb[g3] + 3072)
                       + __ldcg(pb[g3] + 6144) + __ldcg(pb[g3] + 9216);
            const float hold = g_h[t & 1][b0 * HH + k0];
            const float rg = 1.f / (1.f + expf(-(gir + gh[0] + bhr)));
            const float zg = 1.f / (1.f + expf(-(giz + gh[1] + bhz)));
            const float ng = tanhf(gin + rg * (gh[2] + bhn));
            float hnew = (1.f - zg) * ng + zg * hold;
            hnew = p * hold + (1.f - p) * hnew;
            g_h[(t + 1) & 1][b0 * HH + k0] = hnew;
            __nv_bfloat16 hi, lo; split_bf16(hnew, hi, lo);
            g_hbf[(t + 1) & 1][0][b0 * HH + k0] = hi;
            g_hbf[(t + 1) & 1][1][b0 * HH + k0] = lo;
            const size_t ob = (size_t)(t * BB + b0) * HH + k0;
            for (int cp = 0; cp < copies; cp++) out[ob + (size_t)cp * OUT_COPY] = hnew;
            __threadfence();
        }
        grid_bar(phase);
    }
}

// ============================================================
extern "C" void kernel_launch(void* const* d_in, const int* in_sizes, int n_in,
                              void* d_out, int out_size) {
    const float* input    = (const float*)d_in[0];
    const float* paddings = (const float*)d_in[1];
    const float* w_ih     = (const float*)d_in[2];
    const float* w_hh     = (const float*)d_in[3];
    const float* b_ih     = (const float*)d_in[4];
    const float* b_hh     = (const float*)d_in[5];
    float* out = (float*)d_out;

    int copies = out_size / OUT_COPY;
    if (copies < 1) copies = 1;
    if (copies > 2) copies = 2;

    cudaFuncSetAttribute(k_gru, cudaFuncAttributeMaxDynamicSharedMemorySize, SMEM_GRU);

    k_transpose<<<dim3(G3 / 32, HH / 32), dim3(32, 8)>>>(w_hh);
    k_split_x<<<(TT * BB * II) / 256, 256>>>(input);
    k_split_wt<<<dim3(G3 / 32, II / 32), dim3(32, 8)>>>(w_ih);
    k_gemm_gi<<<dim3(G3 / 128, (TT * BB) / 128), 256>>>(b_ih);
    k_gru<<<NCTA, NTHR, SMEM_GRU>>>(paddings, b_hh, out, copies);
}

// round 13
// speedup vs baseline: 1.0041x; 1.0041x over previous
#include <cuda_runtime.h>
#include <cuda_bf16.h>
#include <math.h>
#include <stdint.h>

#define TT 512
#define BB 32
#define II 512
#define HH 1024
#define G3 3072
#define NCTA 128
#define NTHR 256
#define OUT_COPY (TT * BB * HH)

#define KE 1536          // K_eff for input gemm (512*3)
#define WS_ROW 776       // 768 + 8 pad (bf16 elems)
#define WS_BYTES (96 * WS_ROW * 2)          // 148992
#define HS_OFF WS_BYTES
#define SMEM_GRU (WS_BYTES + 32 * WS_ROW * 2)  // 198656

typedef unsigned long long ull;

// -------- static device scratch --------
__device__ float g_gi[(size_t)TT * BB * G3];          // gi = X@w_ih + b_ih
__device__ float g_wT[G3 * HH];                       // w_hh^T fp32 [3H][H]
__device__ __nv_bfloat16 g_xs[(size_t)TT * BB * KE];  // X split [row][hi|hi|lo]
__device__ __nv_bfloat16 g_wst[(size_t)G3 * KE];      // w_ih^T split [n][hi|lo|hi]
__device__ float g_h[2][BB * HH];                     // fp32 hidden [b][k]
__device__ __nv_bfloat16 g_hbf[2][2][BB * HH];        // bf16 hi/lo of h [b][k]
__device__ float g_part[NCTA * BB * 96];              // split-K partials [blk][b][m]
__device__ unsigned g_bar_count = 0;
__device__ volatile unsigned g_bar_phase = 0;

// bf16 mma m16n8k16: D(f32) += A(bf16,row) * B(bf16,col)
static __device__ __forceinline__ void mma_bf16(float* d, const uint32_t* a,
                                                const uint32_t* b) {
    asm volatile(
        "mma.sync.aligned.m16n8k16.row.col.f32.bf16.bf16.f32 "
        "{%0,%1,%2,%3}, {%4,%5,%6,%7}, {%8,%9}, {%0,%1,%2,%3};"
        : "+f"(d[0]), "+f"(d[1]), "+f"(d[2]), "+f"(d[3])
        : "r"(a[0]), "r"(a[1]), "r"(a[2]), "r"(a[3]), "r"(b[0]), "r"(b[1]));
}

static __device__ __forceinline__ void split_bf16(float x, __nv_bfloat16& hi,
                                                  __nv_bfloat16& lo) {
    hi = __float2bfloat16(x);
    lo = __float2bfloat16(x - __bfloat162float(hi));
}

// ============================================================
// Transpose w_hh [H][3H] -> g_wT [3H][H] (fp32)
// ============================================================
__global__ void k_transpose(const float* __restrict__ whh) {
    __shared__ float tile[32][33];
    const int col0 = blockIdx.x * 32;
    const int row0 = blockIdx.y * 32;
    const int tx = threadIdx.x, ty = threadIdx.y;
#pragma unroll
    for (int r = ty; r < 32; r += 8)
        tile[r][tx] = whh[(row0 + r) * G3 + col0 + tx];
    __syncthreads();
#pragma unroll
    for (int r = ty; r < 32; r += 8)
        g_wT[(size_t)(col0 + r) * HH + row0 + tx] = tile[tx][r];
}

// ============================================================
// Split X -> g_xs [hi | hi | lo] along K
// ============================================================
__global__ void k_split_x(const float* __restrict__ X) {
    const size_t idx = (size_t)blockIdx.x * 256 + threadIdx.x;
    const float x = X[idx];
    const size_t r = idx >> 9;          // / 512
    const int k = (int)(idx & 511);
    __nv_bfloat16 hi, lo; split_bf16(x, hi, lo);
    __nv_bfloat16* row = g_xs + r * KE;
    row[k] = hi; row[512 + k] = hi; row[1024 + k] = lo;
}

// ============================================================
// Split+transpose w_ih [512][3072] -> g_wst [3072][hi | lo | hi]
// ============================================================
__global__ void k_split_wt(const float* __restrict__ wih) {
    __shared__ float tile[32][33];
    const int col0 = blockIdx.x * 32;   // 3072 dim
    const int row0 = blockIdx.y * 32;   // 512 dim
    const int tx = threadIdx.x, ty = threadIdx.y;
#pragma unroll
    for (int r = ty; r < 32; r += 8)
        tile[r][tx] = wih[(row0 + r) * G3 + col0 + tx];
    __syncthreads();
#pragma unroll
    for (int r = ty; r < 32; r += 8) {
        const float x = tile[tx][r];
        __nv_bfloat16 hi, lo; split_bf16(x, hi, lo);
        __nv_bfloat16* row = g_wst + (size_t)(col0 + r) * KE + row0 + tx;
        row[0] = hi; row[512] = lo; row[1024] = hi;
    }
}

// ============================================================
// Input GEMM (HMMA bf16x3): gi = X@W + bias.
// M=16384, N=3072, K_eff=1536. BM=BN=128, BK=32, 256 thr (8 warps 4m x 2n).
// ============================================================
__global__ __launch_bounds__(256) void k_gemm_gi(const float* __restrict__ bias) {
    __shared__ __nv_bfloat16 a_s[2][128 * 40];
    __shared__ __nv_bfloat16 b_s[2][128 * 40];

    const int bm = blockIdx.y * 128;
    const int bn = blockIdx.x * 128;
    const int tid = threadIdx.x;
    const int wid = tid >> 5, lane = tid & 31;
    const int g = lane >> 2, tg = lane & 3;
    const int mw = wid & 3, nw = wid >> 2;   // warp tile [mw*32,+32) x [nw*64,+64)

    const int grow = tid >> 1;               // 0..127
    const int gco4 = (tid & 1) * 2;          // uint4 offset within 32-elem chunk

    const uint4* ap = (const uint4*)(g_xs + (size_t)(bm + grow) * KE);
    const uint4* bp = (const uint4*)(g_wst + (size_t)(bn + grow) * KE);

    float acc[2][8][4];
#pragma unroll
    for (int i = 0; i < 2; i++)
#pragma unroll
        for (int j = 0; j < 8; j++)
#pragma unroll
            for (int p = 0; p < 4; p++) acc[i][j][p] = 0.f;

    // prologue: chunk 0
    {
        uint4 av0 = ap[gco4], av1 = ap[gco4 + 1];
        uint4 bv0 = bp[gco4], bv1 = bp[gco4 + 1];
        *(uint4*)&a_s[0][grow * 40 + gco4 * 8] = av0;
        *(uint4*)&a_s[0][grow * 40 + gco4 * 8 + 8] = av1;
        *(uint4*)&b_s[0][grow * 40 + gco4 * 8] = bv0;
        *(uint4*)&b_s[0][grow * 40 + gco4 * 8 + 8] = bv1;
    }
    __syncthreads();

    int buf = 0;
    for (int kc = 0; kc < KE / 32; kc++) {
        uint4 av0, av1, bv0, bv1;
        if (kc < KE / 32 - 1) {
            av0 = ap[(kc + 1) * 4 + gco4]; av1 = ap[(kc + 1) * 4 + gco4 + 1];
            bv0 = bp[(kc + 1) * 4 + gco4]; bv1 = bp[(kc + 1) * 4 + gco4 + 1];
        }
#pragma unroll
        for (int kk = 0; kk < 2; kk++) {
            const int ka = kk * 16 + 2 * tg;
            uint32_t afr[2][4];
#pragma unroll
            for (int mt = 0; mt < 2; mt++) {
                const int ar = mw * 32 + mt * 16 + g;
                afr[mt][0] = *(const uint32_t*)&a_s[buf][ar * 40 + ka];
                afr[mt][1] = *(const uint32_t*)&a_s[buf][(ar + 8) * 40 + ka];
                afr[mt][2] = *(const uint32_t*)&a_s[buf][ar * 40 + ka + 8];
                afr[mt][3] = *(const uint32_t*)&a_s[buf][(ar + 8) * 40 + ka + 8];
            }
#pragma unroll
            for (int nt = 0; nt < 8; nt++) {
                const int br = nw * 64 + nt * 8 + g;
                uint32_t bfr[2];
                bfr[0] = *(const uint32_t*)&b_s[buf][br * 40 + ka];
                bfr[1] = *(const uint32_t*)&b_s[buf][br * 40 + ka + 8];
                mma_bf16(acc[0][nt], afr[0], bfr);
                mma_bf16(acc[1][nt], afr[1], bfr);
            }
        }
        if (kc < KE / 32 - 1) {
            *(uint4*)&a_s[buf ^ 1][grow * 40 + gco4 * 8] = av0;
            *(uint4*)&a_s[buf ^ 1][grow * 40 + gco4 * 8 + 8] = av1;
            *(uint4*)&b_s[buf ^ 1][grow * 40 + gco4 * 8] = bv0;
            *(uint4*)&b_s[buf ^ 1][grow * 40 + gco4 * 8 + 8] = bv1;
            __syncthreads();
            buf ^= 1;
        }
    }

    // epilogue: D[m][n] -> gi[row][col] + bias
#pragma unroll
    for (int mt = 0; mt < 2; mt++) {
        const int row0 = bm + mw * 32 + mt * 16 + g;
#pragma unroll
        for (int nt = 0; nt < 8; nt++) {
            const int col = bn + nw * 64 + nt * 8 + 2 * tg;
            const float bz0 = __ldg(bias + col), bz1 = __ldg(bias + col + 1);
            float2 o0 = make_float2(acc[mt][nt][0] + bz0, acc[mt][nt][1] + bz1);
            float2 o1 = make_float2(acc[mt][nt][2] + bz0, acc[mt][nt][3] + bz1);
            *(float2*)&g_gi[(size_t)row0 * G3 + col] = o0;
            *(float2*)&g_gi[(size_t)(row0 + 8) * G3 + col] = o1;
        }
    }
}

// ============================================================
// Grid-wide barrier (128 CTAs, all wave-1 resident)
// ============================================================
__device__ __forceinline__ void grid_bar(unsigned& phase) {
    __syncthreads();
    if (threadIdx.x == 0) {
        unsigned old = atomicAdd(&g_bar_count, 1u);
        if (old == NCTA - 1) {
            g_bar_count = 0;
            __threadfence();
            g_bar_phase = phase + 1;
        } else {
            while (g_bar_phase == phase) { }
        }
        __threadfence();
    }
    __syncthreads();
    phase++;
}

// ============================================================
// Persistent GRU recurrence (HMMA bf16x3).
// 128 CTAs x 256 thr. blk = cg*4+s: cg -> 96 cols of 3H, s -> K seg of 256.
// w smem [96][776]: [whi|whi|wlo]; h smem [32][776]: [hhi|hlo|hhi].
// GEMM: warps 0..5, warp = m-tile (16 cols), all 4 n-tiles (batch), K_eff=768.
// Partials to g_part; gates distributed over all 128 CTAs (1 item/thread).
// ============================================================
__global__ __launch_bounds__(NTHR, 1) void k_gru(const float* __restrict__ paddings,
                                                 const float* __restrict__ b_hh,
                                                 float* __restrict__ out,
                                                 int copies) {
    extern __shared__ char sm8[];
    __nv_bfloat16* w_s = (__nv_bfloat16*)sm8;            // [96][776]
    __nv_bfloat16* h_s = (__nv_bfloat16*)(sm8 + HS_OFF); // [32][776]
    float* tb = (float*)(sm8 + HS_OFF);                  // alias after GEMM: [32][100]

    const int tid = threadIdx.x;
    const int wid = tid >> 5, lane = tid & 31;
    const int g = lane >> 2, tg = lane & 3;
    const int blk = blockIdx.x, cg = blk >> 2, s = blk & 3;

    // ---- stage w slice once: [96 m][256 k] -> [hi|hi|lo] ----
    for (int idx = tid; idx < 96 * 256; idx += NTHR) {
        const int m = idx >> 8, k = idx & 255;
        __nv_bfloat16 hi, lo;
        split_bf16(g_wT[(size_t)(cg * 96 + m) * HH + s * 256 + k], hi, lo);
        w_s[m * WS_ROW + k] = hi;
        w_s[m * WS_ROW + 256 + k] = hi;
        w_s[m * WS_ROW + 512 + k] = lo;
    }

    // ---- gate-thread constants (all CTAs: 8 hidden dims x 32 batches) ----
    const int k0 = blk * 8 + (tid & 7);
    const int b0 = tid >> 3;
    const float bhr = b_hh[k0], bhz = b_hh[HH + k0], bhn = b_hh[2 * HH + k0];
    const float* pb[3];
#pragma unroll
    for (int g3 = 0; g3 < 3; g3++) {
        const int col = g3 * HH + k0;
        pb[g3] = g_part + (size_t)((col / 96) * 4) * 3072 + b0 * 96 + (col % 96);
    }

    // init h buffer 0
    g_h[0][b0 * HH + k0] = 0.f;
    g_hbf[0][0][b0 * HH + k0] = __float2bfloat16(0.f);
    g_hbf[0][1][b0 * HH + k0] = __float2bfloat16(0.f);
    __threadfence();

    unsigned phase = g_bar_phase;
    grid_bar(phase);

    for (int t = 0; t < TT; t++) {
        // ---- stage h seg: [32 b][256 k] hi/lo -> [hhi|hlo|hhi] ----
        const uint4* hhi = (const uint4*)g_hbf[t & 1][0];
        const uint4* hlo = (const uint4*)g_hbf[t & 1][1];
#pragma unroll 2
        for (int idx = tid; idx < 1024; idx += NTHR) {
            const int b = idx >> 5, u = idx & 31;
            const uint4 vhi = __ldcg(&hhi[b * 128 + s * 32 + u]);
            const uint4 vlo = __ldcg(&hlo[b * 128 + s * 32 + u]);
            __nv_bfloat16* hrow = h_s + b * WS_ROW + u * 8;
            *(uint4*)(hrow) = vhi;
            *(uint4*)(hrow + 256) = vlo;
            *(uint4*)(hrow + 512) = vhi;
        }
        __syncthreads();

        // ---- GEMM: warps 0..5 ----
        float acc[4][4];
        if (wid < 6) {
#pragma unroll
            for (int nt = 0; nt < 4; nt++)
#pragma unroll
                for (int p = 0; p < 4; p++) acc[nt][p] = 0.f;
            const int ar = wid * 16 + g;
#pragma unroll 4
            for (int kk = 0; kk < 48; kk++) {
                const int ka = kk * 16 + 2 * tg;
                uint32_t afr[4];
                afr[0] = *(const uint32_t*)&w_s[ar * WS_ROW + ka];
                afr[1] = *(const uint32_t*)&w_s[(ar + 8) * WS_ROW + ka];
                afr[2] = *(const uint32_t*)&w_s[ar * WS_ROW + ka + 8];
                afr[3] = *(const uint32_t*)&w_s[(ar + 8) * WS_ROW + ka + 8];
#pragma unroll
                for (int nt = 0; nt < 4; nt++) {
                    const int br = nt * 8 + g;
                    uint32_t bfr[2];
                    bfr[0] = *(const uint32_t*)&h_s[br * WS_ROW + ka];
                    bfr[1] = *(const uint32_t*)&h_s[br * WS_ROW + ka + 8];
                    mma_bf16(acc[nt], afr, bfr);
                }
            }
        }
        __syncthreads();   // all h reads done -> tb alias safe

        // ---- epilogue: D frags -> tb[b][m] ----
        if (wid < 6) {
            const int m0 = wid * 16 + g;
#pragma unroll
            for (int nt = 0; nt < 4; nt++) {
                const int bcol = nt * 8 + 2 * tg;
                tb[bcol * 100 + m0] = acc[nt][0];
                tb[(bcol + 1) * 100 + m0] = acc[nt][1];
                tb[bcol * 100 + m0 + 8] = acc[nt][2];
                tb[(bcol + 1) * 100 + m0 + 8] = acc[nt][3];
            }
        }
        __syncthreads();

        // ---- copy tb -> g_part[blk] ----
        float* gp = g_part + (size_t)blk * 3072;
#pragma unroll
        for (int i = tid; i < 768; i += NTHR) {
            const int b = i / 24, o = i - b * 24;
            *(uint4*)&gp[b * 96 + o * 4] = *(const uint4*)&tb[b * 100 + o * 4];
        }
        __threadfence();
        grid_bar(phase);

        // ---- gates (all CTAs, 1 item/thread) ----
        {
            const float* gib = g_gi + (size_t)t * BB * G3 + (size_t)b0 * G3;
            const float gir = __ldg(gib + k0);
            const float giz = __ldg(gib + HH + k0);
            const float gin = __ldg(gib + 2 * HH + k0);
            const float p = __ldg(paddings + t * BB + b0);
            float gh[3];
#pragma unroll
            for (int g3 = 0; g3 < 3; g3++)
                gh[g3] = __ldcg(pb[g3]) + __ldcg(pb[g3] + 3072)
                       + __ldcg(pb[g3] + 6144) + __ldcg(pb[g3] + 9216);
            const float hold = g_h[t & 1][b0 * HH + k0];
            const float rg = 1.f / (1.f + expf(-(gir + gh[0] + bhr)));
            const float zg = 1.f / (1.f + expf(-(giz + gh[1] + bhz)));
            const float ng = tanhf(gin + rg * (gh[2] + bhn));
            float hnew = (1.f - zg) * ng + zg * hold;
            hnew = p * hold + (1.f - p) * hnew;
            g_h[(t + 1) & 1][b0 * HH + k0] = hnew;
            __nv_bfloat16 hi, lo; split_bf16(hnew, hi, lo);
            g_hbf[(t + 1) & 1][0][b0 * HH + k0] = hi;
            g_hbf[(t + 1) & 1][1][b0 * HH + k0] = lo;
            const size_t ob = (size_t)(t * BB + b0) * HH + k0;
            for (int cp = 0; cp < copies; cp++) out[ob + (size_t)cp * OUT_COPY] = hnew;
            __threadfence();
        }
        grid_bar(phase);
    }
}

// ============================================================
extern "C" void kernel_launch(void* const* d_in, const int* in_sizes, int n_in,
                              void* d_out, int out_size) {
    const float* input    = (const float*)d_in[0];
    const float* paddings = (const float*)d_in[1];
    const float* w_ih     = (const float*)d_in[2];
    const float* w_hh     = (const float*)d_in[3];
    const float* b_ih     = (const float*)d_in[4];
    const float* b_hh     = (const float*)d_in[5];
    float* out = (float*)d_out;

    int copies = out_size / OUT_COPY;
    if (copies < 1) copies = 1;
    if (copies > 2) copies = 2;

    cudaFuncSetAttribute(k_gru, cudaFuncAttributeMaxDynamicSharedMemorySize, SMEM_GRU);

    k_transpose<<<dim3(G3 / 32, HH / 32), dim3(32, 8)>>>(w_hh);
    k_split_x<<<(TT * BB * II) / 256, 256>>>(input);
    k_split_wt<<<dim3(G3 / 32, II / 32), dim3(32, 8)>>>(w_ih);
    k_gemm_gi<<<dim3(G3 / 128, (TT * BB) / 128), 256>>>(b_ih);
    k_gru<<<NCTA, NTHR, SMEM_GRU>>>(paddings, b_hh, out, copies);
}